// round 7
// baseline (speedup 1.0000x reference)
#include <cuda_runtime.h>
#include <math_constants.h>

// x: (64, 4096, 256) fp32; top-8 over axis 1 (S), sorted desc -> (64, 8, 256)
#define B_DIM 64
#define S_DIM 4096
#define C_DIM 256
#define K_TOP 8

#define CHUNKS 16
#define CHUNK_S (S_DIM / CHUNKS)        // 256
#define PAIRS_PER_BLOCK 2               // 256 threads = 2 (b,chunk) pairs x 128 lanes
#define GRID1 (B_DIM * CHUNKS / PAIRS_PER_BLOCK)  // 512 blocks
#define BLOCKS_PER_BATCH (CHUNKS / PAIRS_PER_BLOCK) // 8

// Partials, layout [b][chunk][c][k]: 8 MiB static scratch.
__device__ float g_partial[B_DIM * CHUNKS * C_DIM * K_TOP];
// Per-batch completion counters (zero-init; last block resets -> replay-safe).
__device__ int g_cnt[B_DIM];

// Compare-exchange keeping max at 'a' (descending order).
__device__ __forceinline__ void ce(float& a, float& b) {
    float hi = fmaxf(a, b);
    float lo = fminf(a, b);
    a = hi; b = lo;
}

// Batcher odd-even mergesort, n=8, 19 CE, descending.
__device__ __forceinline__ void sort8_desc(float (&f)[8]) {
    ce(f[0],f[1]); ce(f[2],f[3]); ce(f[4],f[5]); ce(f[6],f[7]);
    ce(f[0],f[2]); ce(f[1],f[3]); ce(f[4],f[6]); ce(f[5],f[7]);
    ce(f[1],f[2]); ce(f[5],f[6]);
    ce(f[0],f[4]); ce(f[1],f[5]); ce(f[2],f[6]); ce(f[3],f[7]);
    ce(f[2],f[4]); ce(f[3],f[5]);
    ce(f[1],f[2]); ce(f[3],f[4]); ce(f[5],f[6]);
}

// Exact sorted top-8 of the union of two descending-sorted 8-lists.
__device__ __forceinline__ void merge8_desc(float (&t)[8], const float (&g)[8]) {
    #pragma unroll
    for (int i = 0; i < 8; ++i) t[i] = fmaxf(t[i], g[7 - i]);
    ce(t[0],t[4]); ce(t[1],t[5]); ce(t[2],t[6]); ce(t[3],t[7]);
    ce(t[0],t[2]); ce(t[1],t[3]); ce(t[4],t[6]); ce(t[5],t[7]);
    ce(t[0],t[1]); ce(t[2],t[3]); ce(t[4],t[5]); ce(t[6],t[7]);
}

// Fused: R5's streaming pass (unchanged geometry) + last-block-per-batch merge.
__global__ __launch_bounds__(256, 3) void kmax_fused_kernel(
    const float2* __restrict__ x2, float* __restrict__ out)
{
    const int sub  = threadIdx.x >> 7;          // 0..1
    const int lane = threadIdx.x & 127;         // float2 channel group
    const int pair = blockIdx.x * PAIRS_PER_BLOCK + sub;
    const int batch = pair >> 4;                // / CHUNKS (same for both subs)
    const int chunk = pair & (CHUNKS - 1);

    const float2* __restrict__ p =
        x2 + ((size_t)batch * S_DIM + (size_t)chunk * CHUNK_S) * (C_DIM / 2) + lane;

    float t0[8], t1[8];
    #pragma unroll
    for (int i = 0; i < 8; ++i) { t0[i] = -CUDART_INF_F; t1[i] = -CUDART_INF_F; }

    #pragma unroll 1
    for (int s = 0; s < CHUNK_S; s += 16) {
        float2 buf[16];
        #pragma unroll
        for (int u = 0; u < 16; ++u)
            buf[u] = __ldcs(p + (size_t)(s + u) * (C_DIM / 2));

        float f[8], g[8];
        // channel .x
        #pragma unroll
        for (int u = 0; u < 8; ++u) { f[u] = buf[u].x; g[u] = buf[u + 8].x; }
        sort8_desc(f); sort8_desc(g);
        merge8_desc(f, g);
        merge8_desc(t0, f);
        // channel .y
        #pragma unroll
        for (int u = 0; u < 8; ++u) { f[u] = buf[u].y; g[u] = buf[u + 8].y; }
        sort8_desc(f); sort8_desc(g);
        merge8_desc(f, g);
        merge8_desc(t1, f);
    }

    // Store partials [b][chunk][c][k]: 64B contiguous per thread (4x STG.128).
    {
        const int c0 = lane * 2;
        float4* __restrict__ o = (float4*)(g_partial
            + (((size_t)(batch * CHUNKS + chunk)) * C_DIM + c0) * K_TOP);
        o[0] = make_float4(t0[0], t0[1], t0[2], t0[3]);
        o[1] = make_float4(t0[4], t0[5], t0[6], t0[7]);
        o[2] = make_float4(t1[0], t1[1], t1[2], t1[3]);
        o[3] = make_float4(t1[4], t1[5], t1[6], t1[7]);
    }

    // Completion protocol (threadFenceReduction pattern).
    __threadfence();
    __shared__ int s_last;
    __syncthreads();
    if (threadIdx.x == 0)
        s_last = (atomicAdd(&g_cnt[batch], 1) == BLOCKS_PER_BATCH - 1) ? 1 : 0;
    __syncthreads();
    if (!s_last) return;

    // Last block of this batch: reset counter for next replay, then merge.
    if (threadIdx.x == 0) g_cnt[batch] = 0;
    __threadfence();

    const int c = threadIdx.x;                  // one channel per thread
    const float* __restrict__ base =
        g_partial + ((size_t)batch * CHUNKS * C_DIM) * K_TOP + (size_t)c * K_TOP;

    float m[8];
    {
        float4 a = *(const float4*)(base + 0);
        float4 d = *(const float4*)(base + 4);
        m[0] = a.x; m[1] = a.y; m[2] = a.z; m[3] = a.w;
        m[4] = d.x; m[5] = d.y; m[6] = d.z; m[7] = d.w;
    }
    #pragma unroll
    for (int j = 1; j < CHUNKS; ++j) {
        const float* bj = base + (size_t)j * C_DIM * K_TOP;
        float g[8];
        float4 a = *(const float4*)(bj + 0);
        float4 d = *(const float4*)(bj + 4);
        g[0] = a.x; g[1] = a.y; g[2] = a.z; g[3] = a.w;
        g[4] = d.x; g[5] = d.y; g[6] = d.z; g[7] = d.w;
        merge8_desc(m, g);
    }

    float* __restrict__ o = out + (size_t)batch * K_TOP * C_DIM + c;
    #pragma unroll
    for (int k = 0; k < K_TOP; ++k)
        o[(size_t)k * C_DIM] = m[k];
}

extern "C" void kernel_launch(void* const* d_in, const int* in_sizes, int n_in,
                              void* d_out, int out_size) {
    const float2* x2 = (const float2*)d_in[0];
    float* out = (float*)d_out;
    kmax_fused_kernel<<<GRID1, 256>>>(x2, out);
}

// round 8
// speedup vs baseline: 1.1591x; 1.1591x over previous
#include <cuda_runtime.h>
#include <math_constants.h>

// x: (64, 4096, 256) fp32; top-8 over axis 1 (S), sorted desc -> (64, 8, 256)
#define B_DIM 64
#define S_DIM 4096
#define C_DIM 256
#define K_TOP 8

#define CHUNKS 16
#define CHUNK_S (S_DIM / CHUNKS)        // 256
#define PAIRS_PER_BLOCK 2               // 256 threads = 2 (b,chunk) pairs x 128 lanes
#define GRID1 (B_DIM * CHUNKS / PAIRS_PER_BLOCK)  // 512 blocks

// Partials, layout [b][c][chunk][k]: 8 MiB static scratch.
// For fixed (b,c) the CHUNKS*K_TOP=128 candidates are 512B contiguous.
__device__ float g_partial[B_DIM * C_DIM * CHUNKS * K_TOP];

// Compare-exchange keeping max at 'a' (descending order).
__device__ __forceinline__ void ce(float& a, float& b) {
    float hi = fmaxf(a, b);
    float lo = fminf(a, b);
    a = hi; b = lo;
}

// Batcher odd-even mergesort, n=8, 19 CE, descending.
__device__ __forceinline__ void sort8_desc(float (&f)[8]) {
    ce(f[0],f[1]); ce(f[2],f[3]); ce(f[4],f[5]); ce(f[6],f[7]);
    ce(f[0],f[2]); ce(f[1],f[3]); ce(f[4],f[6]); ce(f[5],f[7]);
    ce(f[1],f[2]); ce(f[5],f[6]);
    ce(f[0],f[4]); ce(f[1],f[5]); ce(f[2],f[6]); ce(f[3],f[7]);
    ce(f[2],f[4]); ce(f[3],f[5]);
    ce(f[1],f[2]); ce(f[3],f[4]); ce(f[5],f[6]);
}

// Exact sorted top-8 of the union of two descending-sorted 8-lists.
__device__ __forceinline__ void merge8_desc(float (&t)[8], const float (&g)[8]) {
    #pragma unroll
    for (int i = 0; i < 8; ++i) t[i] = fmaxf(t[i], g[7 - i]);
    ce(t[0],t[4]); ce(t[1],t[5]); ce(t[2],t[6]); ce(t[3],t[7]);
    ce(t[0],t[2]); ce(t[1],t[3]); ce(t[4],t[6]); ce(t[5],t[7]);
    ce(t[0],t[1]); ce(t[2],t[3]); ce(t[4],t[5]); ce(t[6],t[7]);
}

// Pass 1 (identical to R5's measured-good config): block = 2 (batch,chunk)
// pairs; 128 lanes x float2 = 256 channels; 16 batched LDG.64 per iteration.
__global__ __launch_bounds__(256, 3) void kmax_partial_kernel(
    const float2* __restrict__ x2)
{
    const int sub  = threadIdx.x >> 7;          // 0..1
    const int lane = threadIdx.x & 127;         // float2 channel group
    const int pair = blockIdx.x * PAIRS_PER_BLOCK + sub;
    const int batch = pair >> 4;                // / CHUNKS
    const int chunk = pair & (CHUNKS - 1);

    const float2* __restrict__ p =
        x2 + ((size_t)batch * S_DIM + (size_t)chunk * CHUNK_S) * (C_DIM / 2) + lane;

    float t0[8], t1[8];
    #pragma unroll
    for (int i = 0; i < 8; ++i) { t0[i] = -CUDART_INF_F; t1[i] = -CUDART_INF_F; }

    #pragma unroll 1
    for (int s = 0; s < CHUNK_S; s += 16) {
        float2 buf[16];
        #pragma unroll
        for (int u = 0; u < 16; ++u)
            buf[u] = __ldcs(p + (size_t)(s + u) * (C_DIM / 2));

        float f[8], g[8];
        // channel .x
        #pragma unroll
        for (int u = 0; u < 8; ++u) { f[u] = buf[u].x; g[u] = buf[u + 8].x; }
        sort8_desc(f); sort8_desc(g);
        merge8_desc(f, g);      // f = sorted top-8 of the 16
        merge8_desc(t0, f);
        // channel .y
        #pragma unroll
        for (int u = 0; u < 8; ++u) { f[u] = buf[u].y; g[u] = buf[u + 8].y; }
        sort8_desc(f); sort8_desc(g);
        merge8_desc(f, g);
        merge8_desc(t1, f);
    }

    // Store: layout [b][c][chunk][k]; 64B contiguous per thread (4x STG.128).
    const int c0 = lane * 2;
    float4* __restrict__ o0 = (float4*)(g_partial
        + (((size_t)batch * C_DIM + c0) * CHUNKS + chunk) * K_TOP);
    float4* __restrict__ o1 = (float4*)(g_partial
        + (((size_t)batch * C_DIM + c0 + 1) * CHUNKS + chunk) * K_TOP);
    o0[0] = make_float4(t0[0], t0[1], t0[2], t0[3]);
    o0[1] = make_float4(t0[4], t0[5], t0[6], t0[7]);
    o1[0] = make_float4(t1[0], t1[1], t1[2], t1[3]);
    o1[1] = make_float4(t1[4], t1[5], t1[6], t1[7]);
}

// Pass 2: warp = 4 (b,c) pairs, 8 lanes each. Lane owns 2 chunks (64B),
// merges them locally, then 3 shuffle-xor levels (d=4,2,1). Warp reads a
// contiguous 2KB L2-resident region.
__global__ __launch_bounds__(256) void kmax_merge_kernel(float* __restrict__ out)
{
    const int warp_id = (blockIdx.x * blockDim.x + threadIdx.x) >> 5;
    const int lane = threadIdx.x & 31;
    const int sg = lane >> 3;                   // sub-group 0..3
    const int sl = lane & 7;                    // lane within sub-group
    const int gp = warp_id * 4 + sg;            // global (b,c) pair
    const int b = gp >> 8;                      // / C_DIM
    const int c = gp & (C_DIM - 1);

    // Pair gp occupies 32 float4s. Lane's 2 chunks = 4 consecutive float4s.
    const float4* __restrict__ p4 =
        (const float4*)g_partial + (size_t)gp * 32 + sl * 4;

    float v[8], g[8];
    {
        float4 a0 = p4[0], a1 = p4[1];          // chunk 2*sl (sorted 8)
        float4 b0 = p4[2], b1 = p4[3];          // chunk 2*sl+1 (sorted 8)
        v[0] = a0.x; v[1] = a0.y; v[2] = a0.z; v[3] = a0.w;
        v[4] = a1.x; v[5] = a1.y; v[6] = a1.z; v[7] = a1.w;
        g[0] = b0.x; g[1] = b0.y; g[2] = b0.z; g[3] = b0.w;
        g[4] = b1.x; g[5] = b1.y; g[6] = b1.z; g[7] = b1.w;
    }
    merge8_desc(v, g);                          // local merge, no shuffles

    #pragma unroll
    for (int d = 4; d >= 1; d >>= 1) {
        float h[8];
        #pragma unroll
        for (int i = 0; i < 8; ++i)
            h[i] = __shfl_xor_sync(0xFFFFFFFFu, v[i], d);
        merge8_desc(v, h);
    }

    // All 8 lanes of the sub-group hold the sorted top-8; lane sl writes v[sl].
    out[((size_t)b * K_TOP + sl) * C_DIM + c] = v[sl];
}

extern "C" void kernel_launch(void* const* d_in, const int* in_sizes, int n_in,
                              void* d_out, int out_size) {
    const float2* x2 = (const float2*)d_in[0];
    float* out = (float*)d_out;

    kmax_partial_kernel<<<GRID1, 256>>>(x2);
    // 16384 pairs / 4 per warp = 4096 warps = 512 blocks x 8 warps.
    kmax_merge_kernel<<<512, 256>>>(out);
}